// round 10
// baseline (speedup 1.0000x reference)
#include <cuda_runtime.h>
#include <cstddef>

// 7x7 VALID conv, 4096x4096 fp32 -> 4090x4090 fp32, + bias.
// Block 16x8 = 128 threads; tile 128(w) x 32(h); thread: 4 rows x 8 cols.
// Packed fma.rn.f32x2, single acc family (24.5 fma2/out).
// (1) SW128-swizzled smem tile -> conflict-free strided LDS.128
// (2) (w,w) weight pairs in __constant__ via prep kernel + D2D memcpy
//     (addresses resolved with cudaGetSymbolAddress -- R9's bug was passing
//      the __device__ shadow symbol as a host pointer).

#define IN_W 4096
#define IN_H 4096
#define OUT_W 4090
#define OUT_H 4090

#define TILE_W 128
#define TILE_H 32
#define SM_H (TILE_H + 6)   // 38
#define SM_W 136            // 134 needed, padded (544B rows)

typedef unsigned long long u64;

__constant__ u64 c_wp[60];          // [kr*8+dx] = (w,w); [56] = (bias,bias)
__device__ u64 g_pack[60];

__device__ __forceinline__ u64 pk(float a, float b) {
    u64 r;
    asm("mov.b64 %0, {%1, %2};" : "=l"(r) : "f"(a), "f"(b));
    return r;
}
__device__ __forceinline__ void fma2(u64 &d, u64 a, u64 b) {
    asm("fma.rn.f32x2 %0, %1, %2, %3;" : "=l"(d) : "l"(a), "l"(b), "l"(d));
}
__device__ __forceinline__ u64 add2(u64 a, u64 b) {
    u64 r;
    asm("add.rn.f32x2 %0, %1, %2;" : "=l"(r) : "l"(a), "l"(b));
    return r;
}
__device__ __forceinline__ unsigned sw128(unsigned b) {
    return b ^ ((b >> 3) & 0x70u);
}

__global__ void prep_kernel(const float* __restrict__ w,
                            const float* __restrict__ bias)
{
    const int t = threadIdx.x;
    if (t < 56) {
        const int r = t / 8, c = t % 8;
        float v = (c < 7) ? w[r * 7 + c] : 0.f;
        g_pack[t] = pk(v, v);
    } else if (t == 56) {
        float b = bias[0];
        g_pack[56] = pk(b, b);
    } else if (t < 60) {
        g_pack[t] = 0ull;
    }
}

__global__ __launch_bounds__(128)
void conv7x7_kernel(const float* __restrict__ x,
                    float* __restrict__ out)
{
    __shared__ float tile[SM_H * SM_W];   // SW128-swizzled storage

    const int tx = threadIdx.x;     // 0..15
    const int ty = threadIdx.y;     // 0..7
    const int tid = ty * 16 + tx;   // 0..127

    const int bx = blockIdx.x * TILE_W;
    const int by = blockIdx.y * TILE_H;

    // ---- Load input tile (38 x 136 floats, float4, swizzled stores) ----
    #pragma unroll 1
    for (int i = tid; i < SM_H * (SM_W / 4); i += 128) {
        const int r  = i / (SM_W / 4);
        const int c4 = i - r * (SM_W / 4);
        const int gy = by + r;
        const int gx = bx + c4 * 4;
        float4 v = make_float4(0.f, 0.f, 0.f, 0.f);
        if (gy < IN_H) {
            const float* row = x + (size_t)gy * IN_W;
            if (gx + 4 <= IN_W) {
                v = *reinterpret_cast<const float4*>(row + gx);
            } else if (gx < IN_W) {
                v.x = row[gx];
                if (gx + 1 < IN_W) v.y = row[gx + 1];
                if (gx + 2 < IN_W) v.z = row[gx + 2];
            }
        }
        const unsigned b = (unsigned)(r * SM_W + c4 * 4) * 4u;
        *reinterpret_cast<float4*>(reinterpret_cast<char*>(tile) + sw128(b)) = v;
    }
    __syncthreads();

    // ---- Compute: 4 output rows x 8 cols per thread ----
    const int tx8 = tx * 8;
    const int ry  = ty * 4;

    u64 acc[4][4];                  // acc[ar][v] = (out[2v], out[2v+1])
    #pragma unroll
    for (int a = 0; a < 4; a++)
        #pragma unroll
        for (int v = 0; v < 4; v++) acc[a][v] = 0ull;

    const char* tb = reinterpret_cast<const char*>(tile);

    #pragma unroll
    for (int r = 0; r < 10; r++) {
        // E[m] = (seg[2m], seg[2m+1]), m=0..6 ; swizzled loads
        u64 E[7];
        {
            const unsigned base = (unsigned)((ry + r) * SM_W + tx8) * 4u;
            ulonglong2 q0 = *reinterpret_cast<const ulonglong2*>(tb + sw128(base));
            ulonglong2 q1 = *reinterpret_cast<const ulonglong2*>(tb + sw128(base + 16u));
            ulonglong2 q2 = *reinterpret_cast<const ulonglong2*>(tb + sw128(base + 32u));
            E[0] = q0.x; E[1] = q0.y;
            E[2] = q1.x; E[3] = q1.y;
            E[4] = q2.x; E[5] = q2.y;
            E[6] = *reinterpret_cast<const u64*>(tb + sw128(base + 48u));
        }
        // S[m] = (seg[2m+1], seg[2m+2]) : 2 MOVs each from float aliases of E
        const float* ef = reinterpret_cast<const float*>(E);
        u64 S[6];
        #pragma unroll
        for (int m = 0; m < 6; m++)
            S[m] = pk(ef[2 * m + 1], ef[2 * m + 2]);

        #pragma unroll
        for (int ar = 0; ar < 4; ar++) {
            const int kr = r - ar;
            if (kr >= 0 && kr <= 6) {
                // weight row kr from constant memory (LDC, no L1TEX traffic)
                #pragma unroll
                for (int dx = 0; dx <= 6; dx += 2) {
                    const u64 wv = c_wp[kr * 8 + dx];
                    #pragma unroll
                    for (int v = 0; v < 4; v++)
                        fma2(acc[ar][v], E[v + dx / 2], wv);
                }
                #pragma unroll
                for (int dx = 1; dx <= 5; dx += 2) {
                    const u64 wv = c_wp[kr * 8 + dx];
                    #pragma unroll
                    for (int v = 0; v < 4; v++)
                        fma2(acc[ar][v], S[v + (dx - 1) / 2], wv);
                }
            }
        }
    }

    // ---- Epilogue: packed bias add, 8B stores ----
    const u64 bp = c_wp[56];
    #pragma unroll
    for (int ar = 0; ar < 4; ar++) {
        const int oy = by + ry + ar;
        if (oy < OUT_H) {
            float* orow = out + (size_t)oy * OUT_W;
            #pragma unroll
            for (int v = 0; v < 4; v++) {
                const int ox = bx + tx8 + 2 * v;
                if (ox < OUT_W) {
                    u64 o = add2(acc[ar][v], bp);
                    *reinterpret_cast<u64*>(orow + ox) = o;
                }
            }
        }
    }
}

extern "C" void kernel_launch(void* const* d_in, const int* in_sizes, int n_in,
                              void* d_out, int out_size)
{
    const float* x    = (const float*)d_in[0];
    const float* w    = (const float*)d_in[1];
    const float* bias = (const float*)d_in[2];
    float* out = (float*)d_out;

    prep_kernel<<<1, 64>>>(w, bias);

    // Resolve REAL device addresses of both symbols, then plain D2D copy.
    void* dst = nullptr;
    void* src = nullptr;
    cudaGetSymbolAddress(&dst, c_wp);
    cudaGetSymbolAddress(&src, g_pack);
    cudaMemcpyAsync(dst, src, 60 * sizeof(u64), cudaMemcpyDeviceToDevice);

    dim3 block(16, 8);
    dim3 grid((OUT_W + TILE_W - 1) / TILE_W,   // 32
              (OUT_H + TILE_H - 1) / TILE_H);  // 128
    conv7x7_kernel<<<grid, block>>>(x, out);
}